// round 1
// baseline (speedup 1.0000x reference)
#include <cuda_runtime.h>
#include <math.h>

#define Bn 4
#define Sn 2048
#define Dn 1024
#define Hn 16
#define DHn 64

// Scratch (allocation-free rule: __device__ globals)
__device__ float g_q[(size_t)Bn * Hn * Sn * DHn];     // Q in [B,H,S,dh]; reused as ctx [B,S,D]
__device__ float g_attn[(size_t)Bn * Hn * Sn * DHn];  // attention out [B,H,S,dh]
__device__ float g_kfall[(size_t)Bn * Hn * Sn * DHn]; // fallback if out buffer lacks k/v
__device__ float g_vfall[(size_t)Bn * Hn * Sn * DHn];

// ---------------------------------------------------------------------------
// Generic 128x128x16 fp32 tiled GEMM, 256 threads, 8x8 microtile, reg prefetch.
// MODE 0: C = A@B + bias, scattered to q/k/v in [B,H,S,dh] layout (N=3072)
// MODE 1: C = A@B + bias, plain row-major [M,N] (N=1024)
// ---------------------------------------------------------------------------
template <int MODE>
__global__ __launch_bounds__(256) void gemm_kernel(
    const float* __restrict__ A, const float* __restrict__ Bm,
    const float* __restrict__ bias, float* __restrict__ C0,
    float* __restrict__ Ck, float* __restrict__ Cv, int N) {
  const int K = 1024;
  __shared__ __align__(16) float As[16][128];  // [k][m] (transposed)
  __shared__ __align__(16) float Bs[16][128];  // [k][n]
  const int t = threadIdx.x;
  const int bx = blockIdx.x, by = blockIdx.y;
  const float* Ab = A + (size_t)by * 128 * K;
  const float* Bb = Bm + (size_t)bx * 128;

  const int ar = t >> 2, ac = (t & 3) << 2;   // A loads: rows ar, ar+64
  const int br = t >> 5, bc = (t & 31) << 2;  // B loads: rows br, br+8

  float4 pa0 = *(const float4*)(Ab + (size_t)ar * K + ac);
  float4 pa1 = *(const float4*)(Ab + (size_t)(ar + 64) * K + ac);
  float4 pb0 = *(const float4*)(Bb + (size_t)br * N + bc);
  float4 pb1 = *(const float4*)(Bb + (size_t)(br + 8) * N + bc);

  float c[8][8];
#pragma unroll
  for (int i = 0; i < 8; ++i)
#pragma unroll
    for (int j = 0; j < 8; ++j) c[i][j] = 0.0f;

  const int trow = (t >> 4) << 3, tcol = (t & 15) << 3;
  const int NT = K / 16;
  for (int kt = 0; kt < NT; ++kt) {
    As[ac + 0][ar] = pa0.x; As[ac + 1][ar] = pa0.y;
    As[ac + 2][ar] = pa0.z; As[ac + 3][ar] = pa0.w;
    As[ac + 0][ar + 64] = pa1.x; As[ac + 1][ar + 64] = pa1.y;
    As[ac + 2][ar + 64] = pa1.z; As[ac + 3][ar + 64] = pa1.w;
    *(float4*)&Bs[br][bc] = pb0;
    *(float4*)&Bs[br + 8][bc] = pb1;
    __syncthreads();
    if (kt + 1 < NT) {
      const float* An = Ab + (kt + 1) * 16;
      pa0 = *(const float4*)(An + (size_t)ar * K + ac);
      pa1 = *(const float4*)(An + (size_t)(ar + 64) * K + ac);
      const float* Bq = Bb + (size_t)(kt + 1) * 16 * N;
      pb0 = *(const float4*)(Bq + (size_t)br * N + bc);
      pb1 = *(const float4*)(Bq + (size_t)(br + 8) * N + bc);
    }
#pragma unroll 8
    for (int kk = 0; kk < 16; ++kk) {
      float av[8], bv[8];
      *(float4*)&av[0] = *(const float4*)&As[kk][trow];
      *(float4*)&av[4] = *(const float4*)&As[kk][trow + 4];
      *(float4*)&bv[0] = *(const float4*)&Bs[kk][tcol];
      *(float4*)&bv[4] = *(const float4*)&Bs[kk][tcol + 4];
#pragma unroll
      for (int i = 0; i < 8; ++i)
#pragma unroll
        for (int j = 0; j < 8; ++j) c[i][j] += av[i] * bv[j];
    }
    __syncthreads();
  }

  if (MODE == 0) {
    // whole block maps to exactly one of q/k/v (1024 % 128 == 0)
    const int which = bx >> 3;
    float* Cp = (which == 0) ? C0 : ((which == 1) ? Ck : Cv);
#pragma unroll
    for (int i = 0; i < 8; ++i) {
      const int m = by * 128 + trow + i;
      const int bb = m >> 11, ss = m & 2047;
#pragma unroll
      for (int j = 0; j < 8; ++j) {
        const int n = bx * 128 + tcol + j;
        const float v = c[i][j] + bias[n];
        const int hd = n & 1023;
        const int h = hd >> 6, d = hd & 63;
        Cp[(((size_t)(bb * Hn + h) * Sn + ss) * DHn) + d] = v;
      }
    }
  } else {
#pragma unroll
    for (int i = 0; i < 8; ++i) {
      const int m = by * 128 + trow + i;
#pragma unroll
      for (int j = 0; j < 8; ++j) {
        const int n = bx * 128 + tcol + j;
        C0[(size_t)m * N + n] = c[i][j] + bias[n];
      }
    }
  }
}

// ---------------------------------------------------------------------------
// Causal flash attention, fp32. 64 queries x 64 keys x dh=64 tiles.
// 256 threads as 16x16; thread owns 4x4 of every 64x64 tile.
// Row stats (m,l) live in registers, reduced via shfl across the 16 lanes
// sharing a row group — no smem reductions.
// ---------------------------------------------------------------------------
__global__ __launch_bounds__(256) void attn_kernel(
    const float* __restrict__ Q, const float* __restrict__ K,
    const float* __restrict__ V, float* __restrict__ O) {
  extern __shared__ float smd[];
  float* Qs = smd;                // [64][68] transposed: Qs[k][q]
  float* Ks = smd + 64 * 68;      // [64][68] transposed: Ks[k][key]
  float* Vs = smd + 2 * 64 * 68;  // [64][68] natural:    Vs[key][d]
  float* Ps = smd + 3 * 64 * 68;  // [64][65] natural:    Ps[q][key]

  const int iq = gridDim.x - 1 - blockIdx.x;  // biggest workloads first
  const int bh = blockIdx.y;
  const float* Qb = Q + (size_t)bh * Sn * DHn + (size_t)iq * 64 * DHn;
  const float* Kb = K + (size_t)bh * Sn * DHn;
  const float* Vb = V + (size_t)bh * Sn * DHn;
  float* Ob = O + (size_t)bh * Sn * DHn + (size_t)iq * 64 * DHn;

  const int t = threadIdx.x;
  const int ty = t >> 4, tx = t & 15;

  // Load Q tile, transposed + pre-scaled by 1/sqrt(dh)
#pragma unroll
  for (int i = t; i < 1024; i += 256) {
    const int r = i & 63, cg = i >> 6;
    float4 q4 = *(const float4*)(Qb + r * 64 + cg * 4);
    Qs[(cg * 4 + 0) * 68 + r] = q4.x * 0.125f;
    Qs[(cg * 4 + 1) * 68 + r] = q4.y * 0.125f;
    Qs[(cg * 4 + 2) * 68 + r] = q4.z * 0.125f;
    Qs[(cg * 4 + 3) * 68 + r] = q4.w * 0.125f;
  }

  float acc[4][4];
#pragma unroll
  for (int i = 0; i < 4; ++i)
#pragma unroll
    for (int j = 0; j < 4; ++j) acc[i][j] = 0.0f;
  float mrow[4], lrow[4];
#pragma unroll
  for (int i = 0; i < 4; ++i) { mrow[i] = -1e30f; lrow[i] = 0.0f; }

  for (int jt = 0; jt <= iq; ++jt) {
    __syncthreads();
    const float* Kt = Kb + (size_t)jt * 64 * DHn;
    const float* Vt = Vb + (size_t)jt * 64 * DHn;
#pragma unroll
    for (int i = t; i < 1024; i += 256) {
      const int r = i & 63, cg = i >> 6;
      float4 k4 = *(const float4*)(Kt + r * 64 + cg * 4);
      Ks[(cg * 4 + 0) * 68 + r] = k4.x;
      Ks[(cg * 4 + 1) * 68 + r] = k4.y;
      Ks[(cg * 4 + 2) * 68 + r] = k4.z;
      Ks[(cg * 4 + 3) * 68 + r] = k4.w;
    }
#pragma unroll
    for (int i = t; i < 1024; i += 256) {
      const int r = i >> 4, cc = (i & 15) * 4;
      *(float4*)&Vs[r * 68 + cc] = *(const float4*)(Vt + r * 64 + cc);
    }
    __syncthreads();

    // S = Q @ K^T (scaled)
    float s[4][4];
#pragma unroll
    for (int i = 0; i < 4; ++i)
#pragma unroll
      for (int j = 0; j < 4; ++j) s[i][j] = 0.0f;
#pragma unroll 8
    for (int kk = 0; kk < 64; ++kk) {
      float av[4], bv[4];
      *(float4*)av = *(const float4*)&Qs[kk * 68 + 4 * ty];
      *(float4*)bv = *(const float4*)&Ks[kk * 68 + 4 * tx];
#pragma unroll
      for (int i = 0; i < 4; ++i)
#pragma unroll
        for (int j = 0; j < 4; ++j) s[i][j] += av[i] * bv[j];
    }

    if (jt == iq) {  // causal mask within diagonal tile
#pragma unroll
      for (int i = 0; i < 4; ++i)
#pragma unroll
        for (int j = 0; j < 4; ++j)
          if (4 * tx + j > 4 * ty + i) s[i][j] = -1e30f;
    }

    // online softmax: per-row max/sum via 16-lane shuffles
    float tmax[4];
#pragma unroll
    for (int i = 0; i < 4; ++i) {
      tmax[i] = s[i][0];
#pragma unroll
      for (int j = 1; j < 4; ++j) tmax[i] = fmaxf(tmax[i], s[i][j]);
    }
#pragma unroll
    for (int off = 8; off > 0; off >>= 1)
#pragma unroll
      for (int i = 0; i < 4; ++i)
        tmax[i] = fmaxf(tmax[i], __shfl_xor_sync(0xffffffffu, tmax[i], off));

    float p[4][4], psum[4], alpha[4];
#pragma unroll
    for (int i = 0; i < 4; ++i) {
      const float mnew = fmaxf(mrow[i], tmax[i]);
      alpha[i] = __expf(mrow[i] - mnew);
      mrow[i] = mnew;
      psum[i] = 0.0f;
#pragma unroll
      for (int j = 0; j < 4; ++j) {
        p[i][j] = __expf(s[i][j] - mnew);
        psum[i] += p[i][j];
      }
    }
#pragma unroll
    for (int off = 8; off > 0; off >>= 1)
#pragma unroll
      for (int i = 0; i < 4; ++i)
        psum[i] += __shfl_xor_sync(0xffffffffu, psum[i], off);
#pragma unroll
    for (int i = 0; i < 4; ++i) {
      lrow[i] = lrow[i] * alpha[i] + psum[i];
#pragma unroll
      for (int j = 0; j < 4; ++j) acc[i][j] *= alpha[i];
    }

    // stage P through smem
#pragma unroll
    for (int i = 0; i < 4; ++i)
#pragma unroll
      for (int j = 0; j < 4; ++j)
        Ps[(4 * ty + i) * 65 + 4 * tx + j] = p[i][j];
    __syncthreads();

    // O += P @ V
#pragma unroll 8
    for (int kk = 0; kk < 64; ++kk) {
      float av[4], bv[4];
#pragma unroll
      for (int i = 0; i < 4; ++i) av[i] = Ps[(4 * ty + i) * 65 + kk];
      *(float4*)bv = *(const float4*)&Vs[kk * 68 + 4 * tx];
#pragma unroll
      for (int i = 0; i < 4; ++i)
#pragma unroll
        for (int j = 0; j < 4; ++j) acc[i][j] += av[i] * bv[j];
    }
  }

#pragma unroll
  for (int i = 0; i < 4; ++i) {
    const float inv = 1.0f / lrow[i];
    float4 o;
    o.x = acc[i][0] * inv; o.y = acc[i][1] * inv;
    o.z = acc[i][2] * inv; o.w = acc[i][3] * inv;
    *(float4*)(Ob + (size_t)(4 * ty + i) * 64 + 4 * tx) = o;
  }
}

// [B,H,S,dh] -> [B,S,D]
__global__ __launch_bounds__(256) void transpose_kernel(
    const float* __restrict__ A, float* __restrict__ C) {
  const int idx = blockIdx.x * 256 + threadIdx.x;  // over 2M float4 groups
  const int c4 = idx & 255;
  const int s = (idx >> 8) & 2047;
  const int b = idx >> 19;
  const int hd = c4 << 2;
  const int h = hd >> 6, d = hd & 63;
  float4 v = *(const float4*)(A + (((size_t)(b * Hn + h) * Sn + s) * DHn + d));
  *(float4*)(C + ((size_t)(b * Sn + s) * Dn + hd)) = v;
}

extern "C" void kernel_launch(void* const* d_in, const int* in_sizes, int n_in,
                              void* d_out, int out_size) {
  (void)in_sizes; (void)n_in;
  const float* x = (const float*)d_in[0];
  const float* w_in = (const float*)d_in[1];
  const float* b_in = (const float*)d_in[2];
  const float* w_out = (const float*)d_in[3];
  const float* b_out = (const float*)d_in[4];
  float* out = (float*)d_out;

  const size_t leaf = (size_t)Bn * Sn * Dn;  // 8388608
  float *gq = nullptr, *ga = nullptr, *gk = nullptr, *gv = nullptr;
  cudaGetSymbolAddress((void**)&gq, g_q);
  cudaGetSymbolAddress((void**)&ga, g_attn);

  float *k_out, *v_out;
  if ((size_t)out_size >= 3 * leaf) {  // (out, (k, v)) flattened
    k_out = out + leaf;
    v_out = out + 2 * leaf;
  } else {  // defensive: keep k,v in scratch
    cudaGetSymbolAddress((void**)&gk, g_kfall);
    cudaGetSymbolAddress((void**)&gv, g_vfall);
    k_out = gk;
    v_out = gv;
  }

  // 1) QKV projection, scattered into [B,H,S,dh]
  gemm_kernel<0><<<dim3(24, 64), 256>>>(x, w_in, b_in, gq, k_out, v_out, 3072);

  // 2) causal flash attention
  cudaFuncSetAttribute(attn_kernel, cudaFuncAttributeMaxDynamicSharedMemorySize,
                       70000);
  attn_kernel<<<dim3(32, 64), 256, 68864>>>(gq, k_out, v_out, ga);

  // 3) [B,H,S,dh] -> [B,S,D] (reuse g_q as ctx buffer)
  transpose_kernel<<<8192, 256>>>(ga, gq);

  // 4) output projection
  gemm_kernel<1><<<dim3(8, 64), 256>>>(gq, w_out, b_out, out, nullptr, nullptr,
                                       1024);
}

// round 6
// speedup vs baseline: 1.7915x; 1.7915x over previous
#include <cuda_runtime.h>
#include <math.h>
#include <cstdint>

#define Bn 4
#define Sn 2048
#define Dn 1024
#define Hn 16
#define DHn 64
#define KDIM 1024

// ---------------- scratch (__device__ globals; no allocs allowed) ----------
__device__ float g_q[(size_t)Bn * Hn * Sn * DHn];     // Q in [B,H,S,dh]
__device__ float g_attn[(size_t)Bn * Hn * Sn * DHn];  // attention out [B,H,S,dh]
__device__ float g_kfall[(size_t)Bn * Hn * Sn * DHn];
__device__ float g_vfall[(size_t)Bn * Hn * Sn * DHn];
__device__ float g_wt1[(size_t)3072 * 1024];          // W_in^T  [3072][1024]
__device__ float g_wt2[(size_t)1024 * 1024];          // W_out^T [1024][1024]

__device__ __forceinline__ float to_tf32(float x) {
  float y;
  asm("cvt.rna.tf32.f32 %0, %1;" : "=f"(y) : "f"(x));
  return y;
}

// mma.sync m16n8k8 tf32 (sm_80+; compiles under compute_103)
__device__ __forceinline__ void mma1688(float* c, const uint32_t* a,
                                        const uint32_t* b) {
  asm volatile(
      "mma.sync.aligned.m16n8k8.row.col.f32.tf32.tf32.f32 "
      "{%0,%1,%2,%3}, {%4,%5,%6,%7}, {%8,%9}, {%0,%1,%2,%3};"
      : "+f"(c[0]), "+f"(c[1]), "+f"(c[2]), "+f"(c[3])
      : "r"(a[0]), "r"(a[1]), "r"(a[2]), "r"(a[3]), "r"(b[0]), "r"(b[1]));
}

// ---------------------------------------------------------------------------
// Weight transpose: WT[n][k] = W[k][n]
// ---------------------------------------------------------------------------
__global__ __launch_bounds__(256) void wtrans_kernel(
    const float* __restrict__ W, float* __restrict__ WT, int K, int N) {
  __shared__ float t[32][33];
  const int n0 = blockIdx.x * 32, k0 = blockIdx.y * 32;
  const int tx = threadIdx.x & 31, ty = threadIdx.x >> 5;
#pragma unroll
  for (int i = 0; i < 4; ++i)
    t[ty + i * 8][tx] = W[(size_t)(k0 + ty + i * 8) * N + n0 + tx];
  __syncthreads();
#pragma unroll
  for (int i = 0; i < 4; ++i)
    WT[(size_t)(n0 + ty + i * 8) * K + k0 + tx] = t[tx][ty + i * 8];
}

// ---------------------------------------------------------------------------
// tf32 HMMA GEMM: D[m][n] = sum_k A[m][k]*Bt[n][k] + bias[n]
// CTA 128x128, 8 warps (2x4), warp tile 64x32, KC=32 double buffered.
// MODE 0: A row-major [M][1024]; epilogue scatters q/k/v into [B,H,S,dh]
// MODE 1: A gathered from [B,H,S,dh]; C row-major [M][1024]
// ---------------------------------------------------------------------------
#define KC 32
#define LDT 36                       // padded row stride (floats)
#define TILE_F (128 * LDT)           // 4608 floats per operand tile
#define STAGE_F (2 * TILE_F)         // A+B per stage
#define GEMM_SMEM (2 * STAGE_F * 4)  // 73728 bytes

template <int MODE>
__global__ __launch_bounds__(256) void gemm_mma(
    const float* __restrict__ A, const float* __restrict__ Bt,
    const float* __restrict__ bias, float* __restrict__ C0,
    float* __restrict__ Ck, float* __restrict__ Cv) {
  extern __shared__ __align__(16) float sm[];
  const int tid = threadIdx.x;
  const int m0 = blockIdx.y * 128, n0 = blockIdx.x * 128;
  const int warp = tid >> 5, lane = tid & 31;
  const int g = lane >> 2, c = lane & 3;
  const int wm = (warp & 1) * 64, wn = (warp >> 1) * 32;

  const int ar = tid >> 3, ac = (tid & 7) << 2;  // global-load mapping

  float acc[4][4][4];
#pragma unroll
  for (int mt = 0; mt < 4; ++mt)
#pragma unroll
    for (int nt = 0; nt < 4; ++nt)
#pragma unroll
      for (int r = 0; r < 4; ++r) acc[mt][nt][r] = 0.0f;

  float4 pa[4], pb[4];
  // prefetch chunk 0
#pragma unroll
  for (int i = 0; i < 4; ++i) {
    const int r = ar + i * 32;
    if (MODE == 0) {
      pa[i] = *(const float4*)(A + (size_t)(m0 + r) * KDIM + ac);
    } else {
      const int m = m0 + r, k = ac;
      const int b = m >> 11, s = m & 2047, h = k >> 6, d = k & 63;
      pa[i] = *(const float4*)(A + (((size_t)(b * Hn + h) * Sn + s) * DHn + d));
    }
    pb[i] = *(const float4*)(Bt + (size_t)(n0 + r) * KDIM + ac);
  }

  const int NCH = KDIM / KC;
  for (int ch = 0; ch < NCH; ++ch) {
    const int buf = ch & 1;
    float* As = sm + buf * STAGE_F;
    float* Bs = As + TILE_F;
#pragma unroll
    for (int i = 0; i < 4; ++i) {
      const int r = ar + i * 32;
      float* pA = As + r * LDT + ac;
      pA[0] = to_tf32(pa[i].x); pA[1] = to_tf32(pa[i].y);
      pA[2] = to_tf32(pa[i].z); pA[3] = to_tf32(pa[i].w);
      float* pB = Bs + r * LDT + ac;
      pB[0] = to_tf32(pb[i].x); pB[1] = to_tf32(pb[i].y);
      pB[2] = to_tf32(pb[i].z); pB[3] = to_tf32(pb[i].w);
    }
    __syncthreads();
    if (ch + 1 < NCH) {
      const int kc = (ch + 1) * KC;
#pragma unroll
      for (int i = 0; i < 4; ++i) {
        const int r = ar + i * 32;
        if (MODE == 0) {
          pa[i] = *(const float4*)(A + (size_t)(m0 + r) * KDIM + kc + ac);
        } else {
          const int m = m0 + r, k = kc + ac;
          const int b = m >> 11, s = m & 2047, h = k >> 6, d = k & 63;
          pa[i] =
              *(const float4*)(A + (((size_t)(b * Hn + h) * Sn + s) * DHn + d));
        }
        pb[i] = *(const float4*)(Bt + (size_t)(n0 + r) * KDIM + kc + ac);
      }
    }
    const uint32_t* Au = (const uint32_t*)(sm + buf * STAGE_F);
    const uint32_t* Bu = Au + TILE_F;
#pragma unroll
    for (int ks = 0; ks < KC / 8; ++ks) {
      uint32_t af[4][4], bf[4][2];
#pragma unroll
      for (int mt = 0; mt < 4; ++mt) {
        const int row = wm + mt * 16 + g;
        af[mt][0] = Au[row * LDT + ks * 8 + c];
        af[mt][1] = Au[(row + 8) * LDT + ks * 8 + c];
        af[mt][2] = Au[row * LDT + ks * 8 + c + 4];
        af[mt][3] = Au[(row + 8) * LDT + ks * 8 + c + 4];
      }
#pragma unroll
      for (int nt = 0; nt < 4; ++nt) {
        const int row = wn + nt * 8 + g;
        bf[nt][0] = Bu[row * LDT + ks * 8 + c];
        bf[nt][1] = Bu[row * LDT + ks * 8 + c + 4];
      }
#pragma unroll
      for (int mt = 0; mt < 4; ++mt)
#pragma unroll
        for (int nt = 0; nt < 4; ++nt) mma1688(acc[mt][nt], af[mt], bf[nt]);
    }
    __syncthreads();
  }

  // epilogue: direct float2 stores, bias fused
#pragma unroll
  for (int mt = 0; mt < 4; ++mt) {
#pragma unroll
    for (int nt = 0; nt < 4; ++nt) {
      const int row = m0 + wm + mt * 16 + g;
      const int col = n0 + wn + nt * 8 + 2 * c;
      const float b0 = bias[col], b1 = bias[col + 1];
      float2 v0 = {acc[mt][nt][0] + b0, acc[mt][nt][1] + b1};
      float2 v1 = {acc[mt][nt][2] + b0, acc[mt][nt][3] + b1};
      if (MODE == 0) {
        const int which = col >> 10, hd = col & 1023;
        float* Cp = (which == 0) ? C0 : ((which == 1) ? Ck : Cv);
        const int h = hd >> 6, d = hd & 63;
        const int b = row >> 11, s = row & 2047;
        float* base = Cp + (((size_t)(b * Hn + h) * Sn) * DHn) + d;
        *(float2*)(base + (size_t)s * DHn) = v0;
        *(float2*)(base + (size_t)(s + 8) * DHn) = v1;
      } else {
        *(float2*)&C0[(size_t)row * 1024 + col] = v0;
        *(float2*)&C0[(size_t)(row + 8) * 1024 + col] = v1;
      }
    }
  }
}

// ---------------------------------------------------------------------------
// Causal flash attention, fp32 (known-good — next round's HMMA target).
// ---------------------------------------------------------------------------
__global__ __launch_bounds__(256) void attn_kernel(
    const float* __restrict__ Q, const float* __restrict__ K,
    const float* __restrict__ V, float* __restrict__ O) {
  extern __shared__ float smd[];
  float* Qs = smd;
  float* Ks = smd + 64 * 68;
  float* Vs = smd + 2 * 64 * 68;
  float* Ps = smd + 3 * 64 * 68;

  const int iq = gridDim.x - 1 - blockIdx.x;
  const int bh = blockIdx.y;
  const float* Qb = Q + (size_t)bh * Sn * DHn + (size_t)iq * 64 * DHn;
  const float* Kb = K + (size_t)bh * Sn * DHn;
  const float* Vb = V + (size_t)bh * Sn * DHn;
  float* Ob = O + (size_t)bh * Sn * DHn + (size_t)iq * 64 * DHn;

  const int t = threadIdx.x;
  const int ty = t >> 4, tx = t & 15;

#pragma unroll
  for (int i = t; i < 1024; i += 256) {
    const int r = i & 63, cg = i >> 6;
    float4 q4 = *(const float4*)(Qb + r * 64 + cg * 4);
    Qs[(cg * 4 + 0) * 68 + r] = q4.x * 0.125f;
    Qs[(cg * 4 + 1) * 68 + r] = q4.y * 0.125f;
    Qs[(cg * 4 + 2) * 68 + r] = q4.z * 0.125f;
    Qs[(cg * 4 + 3) * 68 + r] = q4.w * 0.125f;
  }

  float acc[4][4];
#pragma unroll
  for (int i = 0; i < 4; ++i)
#pragma unroll
    for (int j = 0; j < 4; ++j) acc[i][j] = 0.0f;
  float mrow[4], lrow[4];
#pragma unroll
  for (int i = 0; i < 4; ++i) { mrow[i] = -1e30f; lrow[i] = 0.0f; }

  for (int jt = 0; jt <= iq; ++jt) {
    __syncthreads();
    const float* Kt = Kb + (size_t)jt * 64 * DHn;
    const float* Vt = Vb + (size_t)jt * 64 * DHn;
#pragma unroll
    for (int i = t; i < 1024; i += 256) {
      const int r = i & 63, cg = i >> 6;
      float4 k4 = *(const float4*)(Kt + r * 64 + cg * 4);
      Ks[(cg * 4 + 0) * 68 + r] = k4.x;
      Ks[(cg * 4 + 1) * 68 + r] = k4.y;
      Ks[(cg * 4 + 2) * 68 + r] = k4.z;
      Ks[(cg * 4 + 3) * 68 + r] = k4.w;
    }
#pragma unroll
    for (int i = t; i < 1024; i += 256) {
      const int r = i >> 4, cc = (i & 15) * 4;
      *(float4*)&Vs[r * 68 + cc] = *(const float4*)(Vt + r * 64 + cc);
    }
    __syncthreads();

    float s[4][4];
#pragma unroll
    for (int i = 0; i < 4; ++i)
#pragma unroll
      for (int j = 0; j < 4; ++j) s[i][j] = 0.0f;
#pragma unroll 8
    for (int kk = 0; kk < 64; ++kk) {
      float av[4], bv[4];
      *(float4*)av = *(const float4*)&Qs[kk * 68 + 4 * ty];
      *(float4*)bv = *(const float4*)&Ks[kk * 68 + 4 * tx];
#pragma unroll
      for (int i = 0; i < 4; ++i)
#pragma unroll
        for (int j = 0; j < 4; ++j) s[i][j] += av[i] * bv[j];
    }

    if (jt == iq) {
#pragma unroll
      for (int i = 0; i < 4; ++i)
#pragma unroll
        for (int j = 0; j < 4; ++j)
          if (4 * tx + j > 4 * ty + i) s[i][j] = -1e30f;
    }

    float tmax[4];
#pragma unroll
    for (int i = 0; i < 4; ++i) {
      tmax[i] = s[i][0];
#pragma unroll
      for (int j = 1; j < 4; ++j) tmax[i] = fmaxf(tmax[i], s[i][j]);
    }
#pragma unroll
    for (int off = 8; off > 0; off >>= 1)
#pragma unroll
      for (int i = 0; i < 4; ++i)
        tmax[i] = fmaxf(tmax[i], __shfl_xor_sync(0xffffffffu, tmax[i], off));

    float p[4][4], psum[4], alpha[4];
#pragma unroll
    for (int i = 0; i < 4; ++i) {
      const float mnew = fmaxf(mrow[i], tmax[i]);
      alpha[i] = __expf(mrow[i] - mnew);
      mrow[i] = mnew;
      psum[i] = 0.0f;
#pragma unroll
      for (int j = 0; j < 4; ++j) {
        p[i][j] = __expf(s[i][j] - mnew);
        psum[i] += p[i][j];
      }
    }
#pragma unroll
    for (int off = 8; off > 0; off >>= 1)
#pragma unroll
      for (int i = 0; i < 4; ++i)
        psum[i] += __shfl_xor_sync(0xffffffffu, psum[i], off);
#pragma unroll
    for (int i = 0; i < 4; ++i) {
      lrow[i] = lrow[i] * alpha[i] + psum[i];
#pragma unroll
      for (int j = 0; j < 4; ++j) acc[i][j] *= alpha[i];
    }

#pragma unroll
    for (int i = 0; i < 4; ++i)
#pragma unroll
      for (int j = 0; j < 4; ++j)
        Ps[(4 * ty + i) * 65 + 4 * tx + j] = p[i][j];
    __syncthreads();

#pragma unroll 8
    for (int kk = 0; kk < 64; ++kk) {
      float av[4], bv[4];
#pragma unroll
      for (int i = 0; i < 4; ++i) av[i] = Ps[(4 * ty + i) * 65 + kk];
      *(float4*)bv = *(const float4*)&Vs[kk * 68 + 4 * tx];
#pragma unroll
      for (int i = 0; i < 4; ++i)
#pragma unroll
        for (int j = 0; j < 4; ++j) acc[i][j] += av[i] * bv[j];
    }
  }

#pragma unroll
  for (int i = 0; i < 4; ++i) {
    const float inv = 1.0f / lrow[i];
    float4 o;
    o.x = acc[i][0] * inv; o.y = acc[i][1] * inv;
    o.z = acc[i][2] * inv; o.w = acc[i][3] * inv;
    *(float4*)(Ob + (size_t)(4 * ty + i) * 64 + 4 * tx) = o;
  }
}

extern "C" void kernel_launch(void* const* d_in, const int* in_sizes, int n_in,
                              void* d_out, int out_size) {
  (void)in_sizes; (void)n_in;
  const float* x = (const float*)d_in[0];
  const float* w_in = (const float*)d_in[1];
  const float* b_in = (const float*)d_in[2];
  const float* w_out = (const float*)d_in[3];
  const float* b_out = (const float*)d_in[4];
  float* out = (float*)d_out;

  const size_t leaf = (size_t)Bn * Sn * Dn;
  float *gq = nullptr, *ga = nullptr, *wt1 = nullptr, *wt2 = nullptr;
  cudaGetSymbolAddress((void**)&gq, g_q);
  cudaGetSymbolAddress((void**)&ga, g_attn);
  cudaGetSymbolAddress((void**)&wt1, g_wt1);
  cudaGetSymbolAddress((void**)&wt2, g_wt2);

  float *k_out, *v_out;
  if ((size_t)out_size >= 3 * leaf) {
    k_out = out + leaf;
    v_out = out + 2 * leaf;
  } else {
    float *gk, *gv;
    cudaGetSymbolAddress((void**)&gk, g_kfall);
    cudaGetSymbolAddress((void**)&gv, g_vfall);
    k_out = gk;
    v_out = gv;
  }

  cudaFuncSetAttribute(gemm_mma<0>, cudaFuncAttributeMaxDynamicSharedMemorySize,
                       GEMM_SMEM);
  cudaFuncSetAttribute(gemm_mma<1>, cudaFuncAttributeMaxDynamicSharedMemorySize,
                       GEMM_SMEM);
  cudaFuncSetAttribute(attn_kernel, cudaFuncAttributeMaxDynamicSharedMemorySize,
                       70000);

  // 0) transpose weights to K-major [N][K]
  wtrans_kernel<<<dim3(96, 32), 256>>>(w_in, wt1, 1024, 3072);
  wtrans_kernel<<<dim3(32, 32), 256>>>(w_out, wt2, 1024, 1024);

  // 1) QKV projection (tf32 HMMA), scattered into [B,H,S,dh]
  gemm_mma<0><<<dim3(24, 64), 256, GEMM_SMEM>>>(x, wt1, b_in, gq, k_out, v_out);

  // 2) causal flash attention (fp32)
  attn_kernel<<<dim3(32, 64), 256, 68864>>>(gq, k_out, v_out, ga);

  // 3) output projection (tf32 HMMA), A gathered from [B,H,S,dh]
  // FIX: grid was dim3(4,64) (stale from N=256-tile version) -> half of the
  // 1024 output columns were never written. 8 * 128 = 1024.
  gemm_mma<1><<<dim3(8, 64), 256, GEMM_SMEM>>>(ga, wt2, b_out, out, nullptr,
                                               nullptr);
}

// round 7
// speedup vs baseline: 3.2462x; 1.8120x over previous
#include <cuda_runtime.h>
#include <math.h>
#include <cstdint>

#define Bn 4
#define Sn 2048
#define Dn 1024
#define Hn 16
#define DHn 64
#define KDIM 1024

// ---------------- scratch (__device__ globals; no allocs allowed) ----------
__device__ float g_q[(size_t)Bn * Hn * Sn * DHn];     // Q in [B,H,S,dh]
__device__ float g_attn[(size_t)Bn * Hn * Sn * DHn];  // attention out [B,H,S,dh]
__device__ float g_kfall[(size_t)Bn * Hn * Sn * DHn];
__device__ float g_vfall[(size_t)Bn * Hn * Sn * DHn];
__device__ float g_wt1[(size_t)3072 * 1024];          // W_in^T  [3072][1024]
__device__ float g_wt2[(size_t)1024 * 1024];          // W_out^T [1024][1024]

__device__ __forceinline__ float to_tf32(float x) {
  float y;
  asm("cvt.rna.tf32.f32 %0, %1;" : "=f"(y) : "f"(x));
  return y;
}

// mma.sync m16n8k8 tf32 (sm_80+; compiles under compute_103)
__device__ __forceinline__ void mma1688(float* c, const uint32_t* a,
                                        const uint32_t* b) {
  asm volatile(
      "mma.sync.aligned.m16n8k8.row.col.f32.tf32.tf32.f32 "
      "{%0,%1,%2,%3}, {%4,%5,%6,%7}, {%8,%9}, {%0,%1,%2,%3};"
      : "+f"(c[0]), "+f"(c[1]), "+f"(c[2]), "+f"(c[3])
      : "r"(a[0]), "r"(a[1]), "r"(a[2]), "r"(a[3]), "r"(b[0]), "r"(b[1]));
}

// ---------------------------------------------------------------------------
// Weight transpose: WT[n][k] = W[k][n]
// ---------------------------------------------------------------------------
__global__ __launch_bounds__(256) void wtrans_kernel(
    const float* __restrict__ W, float* __restrict__ WT, int K, int N) {
  __shared__ float t[32][33];
  const int n0 = blockIdx.x * 32, k0 = blockIdx.y * 32;
  const int tx = threadIdx.x & 31, ty = threadIdx.x >> 5;
#pragma unroll
  for (int i = 0; i < 4; ++i)
    t[ty + i * 8][tx] = W[(size_t)(k0 + ty + i * 8) * N + n0 + tx];
  __syncthreads();
#pragma unroll
  for (int i = 0; i < 4; ++i)
    WT[(size_t)(n0 + ty + i * 8) * K + k0 + tx] = t[tx][ty + i * 8];
}

// ---------------------------------------------------------------------------
// tf32 HMMA GEMM (validated R6): D[m][n] = sum_k A[m][k]*Bt[n][k] + bias[n]
// ---------------------------------------------------------------------------
#define KC 32
#define LDT 36
#define TILE_F (128 * LDT)
#define STAGE_F (2 * TILE_F)
#define GEMM_SMEM (2 * STAGE_F * 4)

template <int MODE>
__global__ __launch_bounds__(256) void gemm_mma(
    const float* __restrict__ A, const float* __restrict__ Bt,
    const float* __restrict__ bias, float* __restrict__ C0,
    float* __restrict__ Ck, float* __restrict__ Cv) {
  extern __shared__ __align__(16) float sm[];
  const int tid = threadIdx.x;
  const int m0 = blockIdx.y * 128, n0 = blockIdx.x * 128;
  const int warp = tid >> 5, lane = tid & 31;
  const int g = lane >> 2, c = lane & 3;
  const int wm = (warp & 1) * 64, wn = (warp >> 1) * 32;

  const int ar = tid >> 3, ac = (tid & 7) << 2;

  float acc[4][4][4];
#pragma unroll
  for (int mt = 0; mt < 4; ++mt)
#pragma unroll
    for (int nt = 0; nt < 4; ++nt)
#pragma unroll
      for (int r = 0; r < 4; ++r) acc[mt][nt][r] = 0.0f;

  float4 pa[4], pb[4];
#pragma unroll
  for (int i = 0; i < 4; ++i) {
    const int r = ar + i * 32;
    if (MODE == 0) {
      pa[i] = *(const float4*)(A + (size_t)(m0 + r) * KDIM + ac);
    } else {
      const int m = m0 + r, k = ac;
      const int b = m >> 11, s = m & 2047, h = k >> 6, d = k & 63;
      pa[i] = *(const float4*)(A + (((size_t)(b * Hn + h) * Sn + s) * DHn + d));
    }
    pb[i] = *(const float4*)(Bt + (size_t)(n0 + r) * KDIM + ac);
  }

  const int NCH = KDIM / KC;
  for (int ch = 0; ch < NCH; ++ch) {
    const int buf = ch & 1;
    float* As = sm + buf * STAGE_F;
    float* Bs = As + TILE_F;
#pragma unroll
    for (int i = 0; i < 4; ++i) {
      const int r = ar + i * 32;
      float* pA = As + r * LDT + ac;
      pA[0] = to_tf32(pa[i].x); pA[1] = to_tf32(pa[i].y);
      pA[2] = to_tf32(pa[i].z); pA[3] = to_tf32(pa[i].w);
      float* pB = Bs + r * LDT + ac;
      pB[0] = to_tf32(pb[i].x); pB[1] = to_tf32(pb[i].y);
      pB[2] = to_tf32(pb[i].z); pB[3] = to_tf32(pb[i].w);
    }
    __syncthreads();
    if (ch + 1 < NCH) {
      const int kc = (ch + 1) * KC;
#pragma unroll
      for (int i = 0; i < 4; ++i) {
        const int r = ar + i * 32;
        if (MODE == 0) {
          pa[i] = *(const float4*)(A + (size_t)(m0 + r) * KDIM + kc + ac);
        } else {
          const int m = m0 + r, k = kc + ac;
          const int b = m >> 11, s = m & 2047, h = k >> 6, d = k & 63;
          pa[i] =
              *(const float4*)(A + (((size_t)(b * Hn + h) * Sn + s) * DHn + d));
        }
        pb[i] = *(const float4*)(Bt + (size_t)(n0 + r) * KDIM + kc + ac);
      }
    }
    const uint32_t* Au = (const uint32_t*)(sm + buf * STAGE_F);
    const uint32_t* Bu = Au + TILE_F;
#pragma unroll
    for (int ks = 0; ks < KC / 8; ++ks) {
      uint32_t af[4][4], bf[4][2];
#pragma unroll
      for (int mt = 0; mt < 4; ++mt) {
        const int row = wm + mt * 16 + g;
        af[mt][0] = Au[row * LDT + ks * 8 + c];
        af[mt][1] = Au[(row + 8) * LDT + ks * 8 + c];
        af[mt][2] = Au[row * LDT + ks * 8 + c + 4];
        af[mt][3] = Au[(row + 8) * LDT + ks * 8 + c + 4];
      }
#pragma unroll
      for (int nt = 0; nt < 4; ++nt) {
        const int row = wn + nt * 8 + g;
        bf[nt][0] = Bu[row * LDT + ks * 8 + c];
        bf[nt][1] = Bu[row * LDT + ks * 8 + c + 4];
      }
#pragma unroll
      for (int mt = 0; mt < 4; ++mt)
#pragma unroll
        for (int nt = 0; nt < 4; ++nt) mma1688(acc[mt][nt], af[mt], bf[nt]);
    }
    __syncthreads();
  }

#pragma unroll
  for (int mt = 0; mt < 4; ++mt) {
#pragma unroll
    for (int nt = 0; nt < 4; ++nt) {
      const int row = m0 + wm + mt * 16 + g;
      const int col = n0 + wn + nt * 8 + 2 * c;
      const float b0 = bias[col], b1 = bias[col + 1];
      float2 v0 = {acc[mt][nt][0] + b0, acc[mt][nt][1] + b1};
      float2 v1 = {acc[mt][nt][2] + b0, acc[mt][nt][3] + b1};
      if (MODE == 0) {
        const int which = col >> 10, hd = col & 1023;
        float* Cp = (which == 0) ? C0 : ((which == 1) ? Ck : Cv);
        const int h = hd >> 6, d = hd & 63;
        const int b = row >> 11, s = row & 2047;
        float* base = Cp + (((size_t)(b * Hn + h) * Sn) * DHn) + d;
        *(float2*)(base + (size_t)s * DHn) = v0;
        *(float2*)(base + (size_t)(s + 8) * DHn) = v1;
      } else {
        *(float2*)&C0[(size_t)row * 1024 + col] = v0;
        *(float2*)&C0[(size_t)(row + 8) * 1024 + col] = v1;
      }
    }
  }
}

// ---------------------------------------------------------------------------
// Causal flash attention with tf32 HMMA.
// CTA: 128 queries x full head (dh=64). 8 warps; warp w owns q-rows
// [wm, wm+16). Key tiles of 64. Q fragments persistent in registers.
// Smem: Ks [64 keys][68] (K-major), VT [64 d][68 keys] (transposed),
//       Ps: per-warp 16x68 P strip (warp-private -> only __syncwarp).
// ---------------------------------------------------------------------------
#define ATL 68
#define ATTN_SMEM ((64 * ATL + 64 * ATL + 128 * ATL) * 4)  // 69632 B

__global__ __launch_bounds__(256) void attn_mma(
    const float* __restrict__ Q, const float* __restrict__ K,
    const float* __restrict__ V, float* __restrict__ O) {
  extern __shared__ __align__(16) float smd[];
  float* Ks = smd;                 // [64][ATL]
  float* VT = smd + 64 * ATL;      // [64][ATL]
  float* Ps = smd + 2 * 64 * ATL;  // [128][ATL], warp-private 16-row strips

  const int iq = gridDim.x - 1 - blockIdx.x;  // biggest workloads first
  const int bh = blockIdx.y;
  const int tid = threadIdx.x;
  const int warp = tid >> 5, lane = tid & 31;
  const int g = lane >> 2, c = lane & 3;
  const int wm = warp * 16;

  const float* Qw = Q + (size_t)bh * Sn * DHn + (size_t)(iq * 128 + wm) * DHn;
  const float* Kb = K + (size_t)bh * Sn * DHn;
  const float* Vb = V + (size_t)bh * Sn * DHn;
  float* Ob = O + (size_t)bh * Sn * DHn + (size_t)(iq * 128 + wm) * DHn;

  // persistent Q fragments (scaled by 1/sqrt(dh)=0.125, tf32)
  uint32_t aq[8][4];
#pragma unroll
  for (int ks = 0; ks < 8; ++ks) {
    aq[ks][0] = __float_as_uint(to_tf32(Qw[g * DHn + ks * 8 + c] * 0.125f));
    aq[ks][1] =
        __float_as_uint(to_tf32(Qw[(g + 8) * DHn + ks * 8 + c] * 0.125f));
    aq[ks][2] = __float_as_uint(to_tf32(Qw[g * DHn + ks * 8 + c + 4] * 0.125f));
    aq[ks][3] =
        __float_as_uint(to_tf32(Qw[(g + 8) * DHn + ks * 8 + c + 4] * 0.125f));
  }

  float oacc[8][4];
#pragma unroll
  for (int nt = 0; nt < 8; ++nt)
#pragma unroll
    for (int r = 0; r < 4; ++r) oacc[nt][r] = 0.0f;
  float m0 = -1e30f, m1 = -1e30f, l0 = 0.0f, l1 = 0.0f;

  float* Pw = Ps + wm * ATL;
  const uint32_t* Ku = (const uint32_t*)Ks;
  const uint32_t* Vu = (const uint32_t*)VT;
  const uint32_t* Pu = (const uint32_t*)Pw;

  const int ntiles = 2 * iq + 2;
  for (int jt = 0; jt < ntiles; ++jt) {
    __syncthreads();  // protect Ks/VT reuse
    const float* Kt = Kb + (size_t)jt * 64 * DHn;
    const float* Vt = Vb + (size_t)jt * 64 * DHn;
#pragma unroll
    for (int i = tid; i < 1024; i += 256) {
      const int r = i >> 4, c4 = (i & 15) << 2;
      float4 k4 = *(const float4*)(Kt + r * DHn + c4);
      float* kp = Ks + r * ATL + c4;
      kp[0] = to_tf32(k4.x); kp[1] = to_tf32(k4.y);
      kp[2] = to_tf32(k4.z); kp[3] = to_tf32(k4.w);
      float4 v4 = *(const float4*)(Vt + r * DHn + c4);
      VT[(c4 + 0) * ATL + r] = to_tf32(v4.x);
      VT[(c4 + 1) * ATL + r] = to_tf32(v4.y);
      VT[(c4 + 2) * ATL + r] = to_tf32(v4.z);
      VT[(c4 + 3) * ATL + r] = to_tf32(v4.w);
    }
    __syncthreads();

    // S[16][64] = Q @ K^T
    float sacc[8][4];
#pragma unroll
    for (int nt = 0; nt < 8; ++nt) {
#pragma unroll
      for (int r = 0; r < 4; ++r) sacc[nt][r] = 0.0f;
#pragma unroll
      for (int ks = 0; ks < 8; ++ks) {
        uint32_t bk[2];
        bk[0] = Ku[(nt * 8 + g) * ATL + ks * 8 + c];
        bk[1] = Ku[(nt * 8 + g) * ATL + ks * 8 + c + 4];
        mma1688(sacc[nt], aq[ks], bk);
      }
    }

    // causal mask (only the last two tiles of this block can clip)
    if (jt >= 2 * iq) {
      const int row0 = iq * 128 + wm + g;
#pragma unroll
      for (int nt = 0; nt < 8; ++nt) {
        const int col = jt * 64 + nt * 8 + 2 * c;
        if (col > row0) sacc[nt][0] = -1e30f;
        if (col + 1 > row0) sacc[nt][1] = -1e30f;
        if (col > row0 + 8) sacc[nt][2] = -1e30f;
        if (col + 1 > row0 + 8) sacc[nt][3] = -1e30f;
      }
    }

    // online softmax (row spread over 4 lanes: shfl_xor 1,2)
    float r0 = -1e30f, r1 = -1e30f;
#pragma unroll
    for (int nt = 0; nt < 8; ++nt) {
      r0 = fmaxf(r0, fmaxf(sacc[nt][0], sacc[nt][1]));
      r1 = fmaxf(r1, fmaxf(sacc[nt][2], sacc[nt][3]));
    }
#pragma unroll
    for (int off = 1; off <= 2; off <<= 1) {
      r0 = fmaxf(r0, __shfl_xor_sync(0xffffffffu, r0, off));
      r1 = fmaxf(r1, __shfl_xor_sync(0xffffffffu, r1, off));
    }
    const float mn0 = fmaxf(m0, r0), mn1 = fmaxf(m1, r1);
    const float al0 = __expf(m0 - mn0), al1 = __expf(m1 - mn1);
    m0 = mn0; m1 = mn1;

    float ps0 = 0.0f, ps1 = 0.0f;
#pragma unroll
    for (int nt = 0; nt < 8; ++nt) {
      const float p0 = __expf(sacc[nt][0] - m0);
      const float p1 = __expf(sacc[nt][1] - m0);
      const float p2 = __expf(sacc[nt][2] - m1);
      const float p3 = __expf(sacc[nt][3] - m1);
      ps0 += p0 + p1; ps1 += p2 + p3;
      float2 w0 = {to_tf32(p0), to_tf32(p1)};
      float2 w1 = {to_tf32(p2), to_tf32(p3)};
      *(float2*)&Pw[g * ATL + nt * 8 + 2 * c] = w0;
      *(float2*)&Pw[(g + 8) * ATL + nt * 8 + 2 * c] = w1;
    }
#pragma unroll
    for (int off = 1; off <= 2; off <<= 1) {
      ps0 += __shfl_xor_sync(0xffffffffu, ps0, off);
      ps1 += __shfl_xor_sync(0xffffffffu, ps1, off);
    }
    l0 = l0 * al0 + ps0;
    l1 = l1 * al1 + ps1;
#pragma unroll
    for (int nt = 0; nt < 8; ++nt) {
      oacc[nt][0] *= al0; oacc[nt][1] *= al0;
      oacc[nt][2] *= al1; oacc[nt][3] *= al1;
    }
    __syncwarp();  // P strip is warp-private

    // O[16][64] += P @ V   (B operand = VT[d][key])
#pragma unroll
    for (int ks = 0; ks < 8; ++ks) {
      uint32_t ap[4];
      ap[0] = Pu[g * ATL + ks * 8 + c];
      ap[1] = Pu[(g + 8) * ATL + ks * 8 + c];
      ap[2] = Pu[g * ATL + ks * 8 + c + 4];
      ap[3] = Pu[(g + 8) * ATL + ks * 8 + c + 4];
#pragma unroll
      for (int nt = 0; nt < 8; ++nt) {
        uint32_t bv[2];
        bv[0] = Vu[(nt * 8 + g) * ATL + ks * 8 + c];
        bv[1] = Vu[(nt * 8 + g) * ATL + ks * 8 + c + 4];
        mma1688(oacc[nt], ap, bv);
      }
    }
    __syncwarp();  // P strip reuse next iteration
  }

  const float i0 = 1.0f / l0, i1 = 1.0f / l1;
#pragma unroll
  for (int nt = 0; nt < 8; ++nt) {
    float2 v0 = {oacc[nt][0] * i0, oacc[nt][1] * i0};
    float2 v1 = {oacc[nt][2] * i1, oacc[nt][3] * i1};
    *(float2*)(Ob + g * DHn + nt * 8 + 2 * c) = v0;
    *(float2*)(Ob + (g + 8) * DHn + nt * 8 + 2 * c) = v1;
  }
}

extern "C" void kernel_launch(void* const* d_in, const int* in_sizes, int n_in,
                              void* d_out, int out_size) {
  (void)in_sizes; (void)n_in;
  const float* x = (const float*)d_in[0];
  const float* w_in = (const float*)d_in[1];
  const float* b_in = (const float*)d_in[2];
  const float* w_out = (const float*)d_in[3];
  const float* b_out = (const float*)d_in[4];
  float* out = (float*)d_out;

  const size_t leaf = (size_t)Bn * Sn * Dn;
  float *gq = nullptr, *ga = nullptr, *wt1 = nullptr, *wt2 = nullptr;
  cudaGetSymbolAddress((void**)&gq, g_q);
  cudaGetSymbolAddress((void**)&ga, g_attn);
  cudaGetSymbolAddress((void**)&wt1, g_wt1);
  cudaGetSymbolAddress((void**)&wt2, g_wt2);

  float *k_out, *v_out;
  if ((size_t)out_size >= 3 * leaf) {
    k_out = out + leaf;
    v_out = out + 2 * leaf;
  } else {
    float *gk, *gv;
    cudaGetSymbolAddress((void**)&gk, g_kfall);
    cudaGetSymbolAddress((void**)&gv, g_vfall);
    k_out = gk;
    v_out = gv;
  }

  cudaFuncSetAttribute(gemm_mma<0>, cudaFuncAttributeMaxDynamicSharedMemorySize,
                       GEMM_SMEM);
  cudaFuncSetAttribute(gemm_mma<1>, cudaFuncAttributeMaxDynamicSharedMemorySize,
                       GEMM_SMEM);
  cudaFuncSetAttribute(attn_mma, cudaFuncAttributeMaxDynamicSharedMemorySize,
                       ATTN_SMEM);

  // 0) transpose weights to K-major [N][K]
  wtrans_kernel<<<dim3(96, 32), 256>>>(w_in, wt1, 1024, 3072);
  wtrans_kernel<<<dim3(32, 32), 256>>>(w_out, wt2, 1024, 1024);

  // 1) QKV projection (tf32 HMMA), scattered into [B,H,S,dh]
  gemm_mma<0><<<dim3(24, 64), 256, GEMM_SMEM>>>(x, wt1, b_in, gq, k_out, v_out);

  // 2) causal flash attention (tf32 HMMA)
  attn_mma<<<dim3(16, 64), 256, ATTN_SMEM>>>(gq, k_out, v_out, ga);

  // 3) output projection (tf32 HMMA), A gathered from [B,H,S,dh]
  gemm_mma<1><<<dim3(8, 64), 256, GEMM_SMEM>>>(ga, wt2, b_out, out, nullptr,
                                               nullptr);
}

// round 8
// speedup vs baseline: 3.4571x; 1.0649x over previous
#include <cuda_runtime.h>
#include <math.h>
#include <cstdint>

#define Bn 4
#define Sn 2048
#define Dn 1024
#define Hn 16
#define DHn 64
#define KDIM 1024

// ---------------- scratch (__device__ globals; no allocs allowed) ----------
__device__ float g_q[(size_t)Bn * Hn * Sn * DHn];     // Q [B,H,S,dh] scaled+tf32
__device__ float g_attn[(size_t)Bn * Hn * Sn * DHn];  // attention out [B,H,S,dh]
__device__ float g_kfall[(size_t)Bn * Hn * Sn * DHn];
__device__ float g_vfall[(size_t)Bn * Hn * Sn * DHn];
__device__ float g_ka[(size_t)Bn * Hn * Sn * DHn];    // K tf32, dh-cols pc-packed
__device__ float g_vt[(size_t)Bn * Hn * Sn * DHn];    // V^T [B,H,dh,S] tf32, key-cols pc-packed
__device__ float g_wt1[(size_t)3072 * 1024];          // W_in^T  [3072][1024]
__device__ float g_wt2[(size_t)1024 * 1024];          // W_out^T [1024][1024]

__device__ __forceinline__ float to_tf32(float x) {
  float y;
  asm("cvt.rna.tf32.f32 %0, %1;" : "=f"(y) : "f"(x));
  return y;
}

__device__ __forceinline__ void mma1688(float* c, const uint32_t* a,
                                        const uint32_t* b) {
  asm volatile(
      "mma.sync.aligned.m16n8k8.row.col.f32.tf32.tf32.f32 "
      "{%0,%1,%2,%3}, {%4,%5,%6,%7}, {%8,%9}, {%0,%1,%2,%3};"
      : "+f"(c[0]), "+f"(c[1]), "+f"(c[2]), "+f"(c[3])
      : "r"(a[0]), "r"(a[1]), "r"(a[2]), "r"(a[3]), "r"(b[0]), "r"(b[1]));
}

__device__ __forceinline__ uint32_t smem_u32(const void* p) {
  uint32_t a;
  asm("{ .reg .u64 t; cvta.to.shared.u64 t, %1; cvt.u32.u64 %0, t; }"
      : "=r"(a) : "l"(p));
  return a;
}

__device__ __forceinline__ void cpasync16(uint32_t dst, const void* src) {
  asm volatile("cp.async.cg.shared.global [%0], [%1], 16;" ::"r"(dst),
               "l"(src) : "memory");
}

// ---------------------------------------------------------------------------
// Weight transpose: WT[n][k] = W[k][n]
// ---------------------------------------------------------------------------
__global__ __launch_bounds__(256) void wtrans_kernel(
    const float* __restrict__ W, float* __restrict__ WT, int K, int N) {
  __shared__ float t[32][33];
  const int n0 = blockIdx.x * 32, k0 = blockIdx.y * 32;
  const int tx = threadIdx.x & 31, ty = threadIdx.x >> 5;
#pragma unroll
  for (int i = 0; i < 4; ++i)
    t[ty + i * 8][tx] = W[(size_t)(k0 + ty + i * 8) * N + n0 + tx];
  __syncthreads();
#pragma unroll
  for (int i = 0; i < 4; ++i)
    WT[(size_t)(n0 + ty + i * 8) * K + k0 + tx] = t[tx][ty + i * 8];
}

// ---------------------------------------------------------------------------
// prep_k: tf32-round K copy with dh columns pc-packed within 8-chunks.
// pc(j) = 2*(j&3) + (j>>2):  j=0..3 -> 0,2,4,6 ; j=4..7 -> 1,3,5,7
// ---------------------------------------------------------------------------
__global__ __launch_bounds__(256) void prep_k(const float* __restrict__ K,
                                              float* __restrict__ Ka) {
  const size_t i = ((size_t)blockIdx.x * 256 + threadIdx.x) * 4;
  float4 v = *(const float4*)(K + i);
  const int j0 = (int)(i & 63);
  const int off = (j0 & 4) ? 1 : 0;
  float* dst = Ka + (i - j0) + (j0 & ~7) + off;
  dst[0] = to_tf32(v.x);
  dst[2] = to_tf32(v.y);
  dst[4] = to_tf32(v.z);
  dst[6] = to_tf32(v.w);
}

// ---------------------------------------------------------------------------
// prep_vt: tf32-round + transpose V [S][dh] -> VT [dh][S], key cols pc-packed.
// ---------------------------------------------------------------------------
__global__ __launch_bounds__(256) void prep_vt(const float* __restrict__ V,
                                               float* __restrict__ VT) {
  __shared__ float t[32][33];
  const int bh = blockIdx.z;
  const int s0 = blockIdx.x * 32, d0 = blockIdx.y * 32;
  const float* Vb = V + (size_t)bh * Sn * DHn;
  float* Tb = VT + (size_t)bh * Sn * DHn;
  const int tx = threadIdx.x & 31, ty = threadIdx.x >> 5;
#pragma unroll
  for (int i = 0; i < 4; ++i)
    t[ty + i * 8][tx] = to_tf32(Vb[(size_t)(s0 + ty + i * 8) * DHn + d0 + tx]);
  __syncthreads();
  const int sx = (tx & ~7) | (2 * (tx & 3) + ((tx >> 2) & 1));
#pragma unroll
  for (int i = 0; i < 4; ++i)
    Tb[(size_t)(d0 + ty + i * 8) * Sn + s0 + sx] = t[tx][ty + i * 8];
}

// ---------------------------------------------------------------------------
// tf32 HMMA GEMM (validated): D[m][n] = sum_k A[m][k]*Bt[n][k] + bias[n]
// MODE 0: epilogue scatters q/k/v into [B,H,S,dh]; Q gets *0.125 + tf32.
// MODE 1: A gathered from [B,H,S,dh]; C row-major.
// ---------------------------------------------------------------------------
#define KC 32
#define LDT 36
#define TILE_F (128 * LDT)
#define STAGE_F (2 * TILE_F)
#define GEMM_SMEM (2 * STAGE_F * 4)

template <int MODE>
__global__ __launch_bounds__(256) void gemm_mma(
    const float* __restrict__ A, const float* __restrict__ Bt,
    const float* __restrict__ bias, float* __restrict__ C0,
    float* __restrict__ Ck, float* __restrict__ Cv) {
  extern __shared__ __align__(16) float sm[];
  const int tid = threadIdx.x;
  const int m0 = blockIdx.y * 128, n0 = blockIdx.x * 128;
  const int warp = tid >> 5, lane = tid & 31;
  const int g = lane >> 2, c = lane & 3;
  const int wm = (warp & 1) * 64, wn = (warp >> 1) * 32;

  const int ar = tid >> 3, ac = (tid & 7) << 2;

  float acc[4][4][4];
#pragma unroll
  for (int mt = 0; mt < 4; ++mt)
#pragma unroll
    for (int nt = 0; nt < 4; ++nt)
#pragma unroll
      for (int r = 0; r < 4; ++r) acc[mt][nt][r] = 0.0f;

  float4 pa[4], pb[4];
#pragma unroll
  for (int i = 0; i < 4; ++i) {
    const int r = ar + i * 32;
    if (MODE == 0) {
      pa[i] = *(const float4*)(A + (size_t)(m0 + r) * KDIM + ac);
    } else {
      const int m = m0 + r, k = ac;
      const int b = m >> 11, s = m & 2047, h = k >> 6, d = k & 63;
      pa[i] = *(const float4*)(A + (((size_t)(b * Hn + h) * Sn + s) * DHn + d));
    }
    pb[i] = *(const float4*)(Bt + (size_t)(n0 + r) * KDIM + ac);
  }

  const int NCH = KDIM / KC;
  for (int ch = 0; ch < NCH; ++ch) {
    const int buf = ch & 1;
    float* As = sm + buf * STAGE_F;
    float* Bs = As + TILE_F;
#pragma unroll
    for (int i = 0; i < 4; ++i) {
      const int r = ar + i * 32;
      float* pA = As + r * LDT + ac;
      pA[0] = to_tf32(pa[i].x); pA[1] = to_tf32(pa[i].y);
      pA[2] = to_tf32(pa[i].z); pA[3] = to_tf32(pa[i].w);
      float* pB = Bs + r * LDT + ac;
      pB[0] = to_tf32(pb[i].x); pB[1] = to_tf32(pb[i].y);
      pB[2] = to_tf32(pb[i].z); pB[3] = to_tf32(pb[i].w);
    }
    __syncthreads();
    if (ch + 1 < NCH) {
      const int kc = (ch + 1) * KC;
#pragma unroll
      for (int i = 0; i < 4; ++i) {
        const int r = ar + i * 32;
        if (MODE == 0) {
          pa[i] = *(const float4*)(A + (size_t)(m0 + r) * KDIM + kc + ac);
        } else {
          const int m = m0 + r, k = kc + ac;
          const int b = m >> 11, s = m & 2047, h = k >> 6, d = k & 63;
          pa[i] =
              *(const float4*)(A + (((size_t)(b * Hn + h) * Sn + s) * DHn + d));
        }
        pb[i] = *(const float4*)(Bt + (size_t)(n0 + r) * KDIM + kc + ac);
      }
    }
    const uint32_t* Au = (const uint32_t*)(sm + buf * STAGE_F);
    const uint32_t* Bu = Au + TILE_F;
#pragma unroll
    for (int ks = 0; ks < KC / 8; ++ks) {
      uint32_t af[4][4], bf[4][2];
#pragma unroll
      for (int mt = 0; mt < 4; ++mt) {
        const int row = wm + mt * 16 + g;
        af[mt][0] = Au[row * LDT + ks * 8 + c];
        af[mt][1] = Au[(row + 8) * LDT + ks * 8 + c];
        af[mt][2] = Au[row * LDT + ks * 8 + c + 4];
        af[mt][3] = Au[(row + 8) * LDT + ks * 8 + c + 4];
      }
#pragma unroll
      for (int nt = 0; nt < 4; ++nt) {
        const int row = wn + nt * 8 + g;
        bf[nt][0] = Bu[row * LDT + ks * 8 + c];
        bf[nt][1] = Bu[row * LDT + ks * 8 + c + 4];
      }
#pragma unroll
      for (int mt = 0; mt < 4; ++mt)
#pragma unroll
        for (int nt = 0; nt < 4; ++nt) mma1688(acc[mt][nt], af[mt], bf[nt]);
    }
    __syncthreads();
  }

#pragma unroll
  for (int mt = 0; mt < 4; ++mt) {
#pragma unroll
    for (int nt = 0; nt < 4; ++nt) {
      const int row = m0 + wm + mt * 16 + g;
      const int col = n0 + wn + nt * 8 + 2 * c;
      const float b0 = bias[col], b1 = bias[col + 1];
      float2 v0 = {acc[mt][nt][0] + b0, acc[mt][nt][1] + b1};
      float2 v1 = {acc[mt][nt][2] + b0, acc[mt][nt][3] + b1};
      if (MODE == 0) {
        const int which = col >> 10, hd = col & 1023;
        float* Cp = (which == 0) ? C0 : ((which == 1) ? Ck : Cv);
        if (which == 0) {  // Q: pre-scale + tf32-round for attention
          v0.x = to_tf32(v0.x * 0.125f); v0.y = to_tf32(v0.y * 0.125f);
          v1.x = to_tf32(v1.x * 0.125f); v1.y = to_tf32(v1.y * 0.125f);
        }
        const int h = hd >> 6, d = hd & 63;
        const int b = row >> 11, s = row & 2047;
        float* base = Cp + (((size_t)(b * Hn + h) * Sn) * DHn) + d;
        *(float2*)(base + (size_t)s * DHn) = v0;
        *(float2*)(base + (size_t)(s + 8) * DHn) = v1;
      } else {
        *(float2*)&C0[(size_t)row * 1024 + col] = v0;
        *(float2*)&C0[(size_t)(row + 8) * 1024 + col] = v1;
      }
    }
  }
}

// ---------------------------------------------------------------------------
// Causal flash attention, tf32 HMMA, cp.async double-buffered staging,
// fragment-packed smem layouts (float2 LDS, conflict-free @ stride 72).
// ---------------------------------------------------------------------------
#define ATL 72
#define ASMEM ((4 * 64 * ATL + 128 * ATL) * 4)  // 110592 B

__global__ __launch_bounds__(256) void attn_mma(
    const float* __restrict__ Q, const float* __restrict__ Ka,
    const float* __restrict__ Vt, float* __restrict__ O) {
  extern __shared__ __align__(16) float smd[];
  const int iq = gridDim.x - 1 - blockIdx.x;  // biggest workloads first
  const int bh = blockIdx.y;
  const int tid = threadIdx.x;
  const int warp = tid >> 5, lane = tid & 31;
  const int g = lane >> 2, c = lane & 3;
  const int wm = warp * 16;
  const uint32_t sbase = smem_u32(smd);

  const float* Qw = Q + ((size_t)bh * Sn + iq * 128 + wm) * DHn;
  const float* Kb = Ka + (size_t)bh * Sn * DHn;
  const float* Vb = Vt + (size_t)bh * Sn * DHn;  // [dh][S]
  float* Ob = O + ((size_t)bh * Sn + iq * 128 + wm) * DHn;

  // persistent Q fragments (already scaled + tf32-rounded)
  const uint32_t* Qu = (const uint32_t*)Qw;
  uint32_t aq[8][4];
#pragma unroll
  for (int ks = 0; ks < 8; ++ks) {
    aq[ks][0] = Qu[g * DHn + ks * 8 + c];
    aq[ks][1] = Qu[(g + 8) * DHn + ks * 8 + c];
    aq[ks][2] = Qu[g * DHn + ks * 8 + c + 4];
    aq[ks][3] = Qu[(g + 8) * DHn + ks * 8 + c + 4];
  }

  float oacc[8][4];
#pragma unroll
  for (int nt = 0; nt < 8; ++nt)
#pragma unroll
    for (int r = 0; r < 4; ++r) oacc[nt][r] = 0.0f;
  float m0 = -1e30f, m1 = -1e30f, l0 = 0.0f, l1 = 0.0f;

  float* Pw = smd + 4 * 64 * ATL + wm * ATL;
  const uint32_t* Pu = (const uint32_t*)Pw;
  const int p0pos = ((c & 1) << 2) | (c >> 1);  // pc(2c): 0,4,1,5

  const int ntiles = 2 * iq + 2;

  // prologue: stage tile 0 into buf 0
  {
    const float* Kt = Kb + (size_t)0;
#pragma unroll
    for (int k = 0; k < 4; ++k) {
      const int idx = tid + k * 256;
      const int r = idx >> 4, c4 = (idx & 15) << 2;
      cpasync16(sbase + (uint32_t)(r * ATL + c4) * 4, Kt + r * 64 + c4);
      cpasync16(sbase + (uint32_t)((2 * 64 * ATL) + r * ATL + c4) * 4,
                Vb + (size_t)r * Sn + c4);
    }
    asm volatile("cp.async.commit_group;" ::: "memory");
  }

  for (int jt = 0; jt < ntiles; ++jt) {
    const int buf = jt & 1;
    if (jt + 1 < ntiles) {
      const int nb = buf ^ 1;
      const float* Kt = Kb + (size_t)(jt + 1) * 64 * DHn;
      const float* Vtt = Vb + (size_t)(jt + 1) * 64;
#pragma unroll
      for (int k = 0; k < 4; ++k) {
        const int idx = tid + k * 256;
        const int r = idx >> 4, c4 = (idx & 15) << 2;
        cpasync16(sbase + (uint32_t)(nb * 64 * ATL + r * ATL + c4) * 4,
                  Kt + r * 64 + c4);
        cpasync16(
            sbase + (uint32_t)((2 + nb) * 64 * ATL + r * ATL + c4) * 4,
            Vtt + (size_t)r * Sn + c4);
      }
      asm volatile("cp.async.commit_group;" ::: "memory");
      asm volatile("cp.async.wait_group 1;" ::: "memory");
    } else {
      asm volatile("cp.async.wait_group 0;" ::: "memory");
    }
    __syncthreads();

    const uint32_t* Ku = (const uint32_t*)(smd + buf * 64 * ATL);
    const uint32_t* Vu = (const uint32_t*)(smd + (2 + buf) * 64 * ATL);

    // S[16][64] = Q @ K^T  (packed float2 B fragments)
    float sacc[8][4];
#pragma unroll
    for (int nt = 0; nt < 8; ++nt) {
#pragma unroll
      for (int r = 0; r < 4; ++r) sacc[nt][r] = 0.0f;
#pragma unroll
      for (int ks = 0; ks < 8; ++ks) {
        const uint2 b2 = *(const uint2*)&Ku[(nt * 8 + g) * ATL + ks * 8 + 2 * c];
        const uint32_t bk[2] = {b2.x, b2.y};
        mma1688(sacc[nt], aq[ks], bk);
      }
    }

    // causal mask (only the last two tiles of this block clip)
    if (jt >= 2 * iq) {
      const int row0 = iq * 128 + wm + g;
#pragma unroll
      for (int nt = 0; nt < 8; ++nt) {
        const int col = jt * 64 + nt * 8 + 2 * c;
        if (col > row0) sacc[nt][0] = -1e30f;
        if (col + 1 > row0) sacc[nt][1] = -1e30f;
        if (col > row0 + 8) sacc[nt][2] = -1e30f;
        if (col + 1 > row0 + 8) sacc[nt][3] = -1e30f;
      }
    }

    // online softmax (row over 4 lanes: shfl_xor 1,2)
    float r0 = -1e30f, r1 = -1e30f;
#pragma unroll
    for (int nt = 0; nt < 8; ++nt) {
      r0 = fmaxf(r0, fmaxf(sacc[nt][0], sacc[nt][1]));
      r1 = fmaxf(r1, fmaxf(sacc[nt][2], sacc[nt][3]));
    }
#pragma unroll
    for (int off = 1; off <= 2; off <<= 1) {
      r0 = fmaxf(r0, __shfl_xor_sync(0xffffffffu, r0, off));
      r1 = fmaxf(r1, __shfl_xor_sync(0xffffffffu, r1, off));
    }
    const float mn0 = fmaxf(m0, r0), mn1 = fmaxf(m1, r1);
    const float al0 = __expf(m0 - mn0), al1 = __expf(m1 - mn1);
    m0 = mn0; m1 = mn1;

    float ps0 = 0.0f, ps1 = 0.0f;
#pragma unroll
    for (int nt = 0; nt < 8; ++nt) {
      const float p0 = __expf(sacc[nt][0] - m0);
      const float p1 = __expf(sacc[nt][1] - m0);
      const float p2 = __expf(sacc[nt][2] - m1);
      const float p3 = __expf(sacc[nt][3] - m1);
      ps0 += p0 + p1; ps1 += p2 + p3;
      // store P in pc-packed key positions (matches VT packing)
      float* pr0 = Pw + g * ATL + nt * 8 + p0pos;
      float* pr1 = Pw + (g + 8) * ATL + nt * 8 + p0pos;
      pr0[0] = to_tf32(p0); pr0[2] = to_tf32(p1);
      pr1[0] = to_tf32(p2); pr1[2] = to_tf32(p3);
    }
#pragma unroll
    for (int off = 1; off <= 2; off <<= 1) {
      ps0 += __shfl_xor_sync(0xffffffffu, ps0, off);
      ps1 += __shfl_xor_sync(0xffffffffu, ps1, off);
    }
    l0 = l0 * al0 + ps0;
    l1 = l1 * al1 + ps1;
#pragma unroll
    for (int nt = 0; nt < 8; ++nt) {
      oacc[nt][0] *= al0; oacc[nt][1] *= al0;
      oacc[nt][2] *= al1; oacc[nt][3] *= al1;
    }
    __syncwarp();  // P strip is warp-private

    // O[16][64] += P @ V  (packed float2 A and B fragments)
#pragma unroll
    for (int ks = 0; ks < 8; ++ks) {
      const uint2 a02 = *(const uint2*)&Pu[g * ATL + ks * 8 + 2 * c];
      const uint2 a13 = *(const uint2*)&Pu[(g + 8) * ATL + ks * 8 + 2 * c];
      const uint32_t ap[4] = {a02.x, a13.x, a02.y, a13.y};
#pragma unroll
      for (int nt = 0; nt < 8; ++nt) {
        const uint2 b2 = *(const uint2*)&Vu[(nt * 8 + g) * ATL + ks * 8 + 2 * c];
        const uint32_t bv[2] = {b2.x, b2.y};
        mma1688(oacc[nt], ap, bv);
      }
    }
    __syncthreads();  // all reads of buf done before it is restaged
  }

  const float i0 = 1.0f / l0, i1 = 1.0f / l1;
#pragma unroll
  for (int nt = 0; nt < 8; ++nt) {
    float2 v0 = {oacc[nt][0] * i0, oacc[nt][1] * i0};
    float2 v1 = {oacc[nt][2] * i1, oacc[nt][3] * i1};
    *(float2*)(Ob + g * DHn + nt * 8 + 2 * c) = v0;
    *(float2*)(Ob + (g + 8) * DHn + nt * 8 + 2 * c) = v1;
  }
}

extern "C" void kernel_launch(void* const* d_in, const int* in_sizes, int n_in,
                              void* d_out, int out_size) {
  (void)in_sizes; (void)n_in;
  const float* x = (const float*)d_in[0];
  const float* w_in = (const float*)d_in[1];
  const float* b_in = (const float*)d_in[2];
  const float* w_out = (const float*)d_in[3];
  const float* b_out = (const float*)d_in[4];
  float* out = (float*)d_out;

  const size_t leaf = (size_t)Bn * Sn * Dn;
  float *gq = nullptr, *ga = nullptr, *wt1 = nullptr, *wt2 = nullptr;
  float *gka = nullptr, *gvt = nullptr;
  cudaGetSymbolAddress((void**)&gq, g_q);
  cudaGetSymbolAddress((void**)&ga, g_attn);
  cudaGetSymbolAddress((void**)&wt1, g_wt1);
  cudaGetSymbolAddress((void**)&wt2, g_wt2);
  cudaGetSymbolAddress((void**)&gka, g_ka);
  cudaGetSymbolAddress((void**)&gvt, g_vt);

  float *k_out, *v_out;
  if ((size_t)out_size >= 3 * leaf) {
    k_out = out + leaf;
    v_out = out + 2 * leaf;
  } else {
    float *gk, *gv;
    cudaGetSymbolAddress((void**)&gk, g_kfall);
    cudaGetSymbolAddress((void**)&gv, g_vfall);
    k_out = gk;
    v_out = gv;
  }

  cudaFuncSetAttribute(gemm_mma<0>, cudaFuncAttributeMaxDynamicSharedMemorySize,
                       GEMM_SMEM);
  cudaFuncSetAttribute(gemm_mma<1>, cudaFuncAttributeMaxDynamicSharedMemorySize,
                       GEMM_SMEM);
  cudaFuncSetAttribute(attn_mma, cudaFuncAttributeMaxDynamicSharedMemorySize,
                       ASMEM);

  // 0) transpose weights to K-major [N][K]
  wtrans_kernel<<<dim3(96, 32), 256>>>(w_in, wt1, 1024, 3072);
  wtrans_kernel<<<dim3(32, 32), 256>>>(w_out, wt2, 1024, 1024);

  // 1) QKV projection; Q pre-scaled+rounded into g_q, exact k/v to outputs
  gemm_mma<0><<<dim3(24, 64), 256, GEMM_SMEM>>>(x, wt1, b_in, gq, k_out, v_out);

  // 2) attention operand prep: rounded+packed K, rounded+transposed+packed V
  prep_k<<<8192, 256>>>(k_out, gka);
  prep_vt<<<dim3(64, 2, 64), 256>>>(v_out, gvt);

  // 3) causal flash attention (tf32 HMMA, cp.async pipeline)
  attn_mma<<<dim3(16, 64), 256, ASMEM>>>(gq, gka, gvt, ga);

  // 4) output projection, A gathered from [B,H,S,dh]
  gemm_mma<1><<<dim3(8, 64), 256, GEMM_SMEM>>>(ga, wt2, b_out, out, nullptr,
                                               nullptr);
}